// round 2
// baseline (speedup 1.0000x reference)
#include <cuda_runtime.h>
#include <cstdint>

// Problem constants
#define NROWS   32768      // B * H * W  (8 * 4096)
#define NCODES  8192
#define DIM     64
#define NPB     4096       // H*W per batch
#define QELEMS  2097152    // B*H*W*C

#define NSPLIT  8          // codebook splits per row-tile
#define KPS     (NCODES / NSPLIT)   // 1024 codes per split

// d_out layout (fp32, concatenated in reference return order):
// [0 .. 2097151]  quant_out (flat-identical to x's NCHW layout)
// [2097152]       commitment_loss
// [2097153]       codebook_loss
// [2097154 .. ]   min_encoding_indices (32768, as float)

__device__ float              g_eNorm[NCODES];
__device__ unsigned long long g_key[NROWS];   // ordered(dist)<<32 | code
__device__ float              g_part[512];

struct __align__(16) ull2 { unsigned long long x, y; };

__device__ __forceinline__ unsigned long long pack_dup(float v) {
    unsigned long long r;
    asm("mov.b64 %0, {%1, %1};" : "=l"(r) : "f"(v));
    return r;
}
__device__ __forceinline__ void ffma2(unsigned long long& acc,
                                      unsigned long long a,
                                      unsigned long long b) {
    asm("fma.rn.f32x2 %0, %1, %2, %0;" : "+l"(acc) : "l"(a), "l"(b));
}
__device__ __forceinline__ void unpack2(unsigned long long v, float& lo, float& hi) {
    asm("mov.b64 {%0, %1}, %2;" : "=f"(lo), "=f"(hi) : "l"(v));
}
// Monotone total-order encoding of float into uint32.
__device__ __forceinline__ unsigned int ordered_f32(float f) {
    unsigned int u = __float_as_uint(f);
    return (u & 0x80000000u) ? ~u : (u | 0x80000000u);
}

// ---------------------------------------------------------------------------
// Kernel 0: init keys + codebook squared norms
// ---------------------------------------------------------------------------
__global__ void prep_kernel(const float* __restrict__ emb) {
    int t = blockIdx.x * blockDim.x + threadIdx.x;   // 0..32767
    g_key[t] = 0xFFFFFFFFFFFFFFFFull;
    if (t < NCODES) {
        const float4* r = (const float4*)(emb + (size_t)t * DIM);
        float s = 0.f;
#pragma unroll
        for (int i = 0; i < DIM / 4; i++) {
            float4 v = r[i];
            s += v.x * v.x + v.y * v.y + v.z * v.z + v.w * v.w;
        }
        g_eNorm[t] = s;
    }
}

// ---------------------------------------------------------------------------
// Kernel 1: distance GEMM + argmin over a 1/8 codebook split.
//   grid 2048 = 256 row-tiles x 8 splits; 256 threads.
//   CTA tile: 128 rows x 1024 codes (16 chunks of 64).
//   thread microtile: 8 rows x 4 codes; row-pairs packed as f32x2.
// ---------------------------------------------------------------------------
__global__ void __launch_bounds__(256, 2)
vq_main(const float* __restrict__ x, const float* __restrict__ emb) {
    __shared__ float Xs[DIM][128];   // 32 KB
    __shared__ float Es[DIM][64];    // 16 KB

    const int tid = threadIdx.x;
    const int tx = tid & 15;   // code group (4 codes)
    const int ty = tid >> 4;   // row group (8 rows)

    const int rowtile = blockIdx.x >> 3;
    const int split   = blockIdx.x & 7;
    const int rowbase = rowtile * 128;
    const int b  = rowbase >> 12;
    const int n0 = rowbase & 4095;
    const float* xb = x + (size_t)b * 262144 + n0;   // x[b][c][n] : b*262144 + c*4096 + n

    // Load X tile: Xs[d][i] = xb[d*4096 + i]   (coalesced)
    for (int q = tid; q < 2048; q += 256) {
        int d  = q >> 5;
        int i4 = q & 31;
        *(float4*)&Xs[d][i4 * 4] = *(const float4*)(xb + (size_t)d * NPB + i4 * 4);
    }

    float minv[8];
    int   mini[8];
#pragma unroll
    for (int i = 0; i < 8; i++) { minv[i] = 3.4e38f; mini[i] = 0; }

    unsigned long long acc[4][4];
    const int kbase0 = split * KPS;

    for (int ch = 0; ch < KPS / 64; ch++) {
        const int kbase = kbase0 + ch * 64;
        __syncthreads();   // covers Xs fill (ch=0) and prior-chunk Es readers

        // Load + transpose E chunk: Es[d][j] = emb[(kbase+j)*64 + d]
        for (int q = tid; q < 1024; q += 256) {
            int j  = q >> 4;
            int dg = q & 15;
            float4 v = *(const float4*)(emb + (size_t)(kbase + j) * DIM + dg * 4);
            Es[dg * 4 + 0][j] = v.x;
            Es[dg * 4 + 1][j] = v.y;
            Es[dg * 4 + 2][j] = v.z;
            Es[dg * 4 + 3][j] = v.w;
        }
        __syncthreads();

#pragma unroll
        for (int r = 0; r < 4; r++)
#pragma unroll
            for (int j = 0; j < 4; j++) acc[r][j] = 0ULL;

#pragma unroll 8
        for (int d = 0; d < DIM; d++) {
            ull2 a01 = *(const ull2*)&Xs[d][ty * 8];       // rows (0,1),(2,3)
            ull2 a23 = *(const ull2*)&Xs[d][ty * 8 + 4];   // rows (4,5),(6,7)
            float4 bv = *(const float4*)&Es[d][tx * 4];
            unsigned long long b0 = pack_dup(bv.x);
            unsigned long long b1 = pack_dup(bv.y);
            unsigned long long b2 = pack_dup(bv.z);
            unsigned long long b3 = pack_dup(bv.w);

            ffma2(acc[0][0], a01.x, b0); ffma2(acc[0][1], a01.x, b1);
            ffma2(acc[0][2], a01.x, b2); ffma2(acc[0][3], a01.x, b3);
            ffma2(acc[1][0], a01.y, b0); ffma2(acc[1][1], a01.y, b1);
            ffma2(acc[1][2], a01.y, b2); ffma2(acc[1][3], a01.y, b3);
            ffma2(acc[2][0], a23.x, b0); ffma2(acc[2][1], a23.x, b1);
            ffma2(acc[2][2], a23.x, b2); ffma2(acc[2][3], a23.x, b3);
            ffma2(acc[3][0], a23.y, b0); ffma2(acc[3][1], a23.y, b1);
            ffma2(acc[3][2], a23.y, b2); ffma2(acc[3][3], a23.y, b3);
        }

        // dist = ||e||^2 - 2*dot ; running first-min (ascending code order)
        const float4 en4 = *(const float4*)&g_eNorm[kbase + tx * 4];
        const float en[4] = { en4.x, en4.y, en4.z, en4.w };
#pragma unroll
        for (int j = 0; j < 4; j++) {
            const int code = kbase + tx * 4 + j;
#pragma unroll
            for (int r = 0; r < 4; r++) {
                float lo, hi;
                unpack2(acc[r][j], lo, hi);
                float dlo = fmaf(-2.f, lo, en[j]);
                float dhi = fmaf(-2.f, hi, en[j]);
                if (dlo < minv[2 * r])     { minv[2 * r]     = dlo; mini[2 * r]     = code; }
                if (dhi < minv[2 * r + 1]) { minv[2 * r + 1] = dhi; mini[2 * r + 1] = code; }
            }
        }
    }

    // Reduce across the 16 code-lanes sharing the same ty (one 16-lane half-warp).
#pragma unroll
    for (int i = 0; i < 8; i++) {
        float v = minv[i];
        int   id = mini[i];
#pragma unroll
        for (int off = 8; off; off >>= 1) {
            float ov = __shfl_xor_sync(0xffffffffu, v, off);
            int   oi = __shfl_xor_sync(0xffffffffu, id, off);
            if (ov < v || (ov == v && oi < id)) { v = ov; id = oi; }
        }
        if (tx == 0) {
            unsigned long long key =
                ((unsigned long long)ordered_f32(v) << 32) | (unsigned int)id;
            atomicMin(&g_key[rowbase + ty * 8 + i], key);
        }
    }
}

// ---------------------------------------------------------------------------
// Kernel 2: gather quantized vectors + loss partials + index output
//   grid 512 blocks: (b, 64-wide n tile). Deterministic tree reduction.
// ---------------------------------------------------------------------------
__global__ void __launch_bounds__(256)
gather_loss(const float* __restrict__ x, const float* __restrict__ emb,
            float* __restrict__ qout, float* __restrict__ idx_out_f) {
    __shared__ int   sIdx[64];
    __shared__ float red[256];
    const int blk = blockIdx.x;
    const int b   = blk >> 6;
    const int n0  = (blk & 63) << 6;
    const int tid = threadIdx.x;

    if (tid < 64) {
        int r = b * NPB + n0 + tid;
        int id = (int)(g_key[r] & 0xFFFFFFFFull);
        sIdx[tid] = id;
        idx_out_f[r] = (float)id;
    }
    __syncthreads();

    float s = 0.f;
    const size_t base = (size_t)b * 262144 + n0;
#pragma unroll
    for (int it = 0; it < 16; it++) {
        int e  = tid + (it << 8);
        int c  = e >> 6;
        int nn = e & 63;
        float q  = emb[(size_t)sIdx[nn] * DIM + c];
        size_t off = base + (size_t)c * NPB + nn;
        float xv = x[off];
        float dd = q - xv;
        qout[off] = xv + dd;   // straight-through arithmetic, matches reference
        s += dd * dd;
    }

    red[tid] = s;
    __syncthreads();
    for (int st = 128; st; st >>= 1) {
        if (tid < st) red[tid] += red[tid + st];
        __syncthreads();
    }
    if (tid == 0) g_part[blk] = red[0];
}

// ---------------------------------------------------------------------------
// Kernel 3: finalize losses
// ---------------------------------------------------------------------------
__global__ void finalize(float* __restrict__ out) {
    __shared__ float red[512];
    int t = threadIdx.x;
    red[t] = g_part[t];
    __syncthreads();
    for (int st = 256; st; st >>= 1) {
        if (t < st) red[t] += red[t + st];
        __syncthreads();
    }
    if (t == 0) {
        float l = red[0] * (1.0f / (float)QELEMS);
        out[QELEMS]     = l;  // commitment_loss
        out[QELEMS + 1] = l;  // codebook_loss (identical value)
    }
}

// ---------------------------------------------------------------------------
extern "C" void kernel_launch(void* const* d_in, const int* in_sizes, int n_in,
                              void* d_out, int out_size) {
    const float* x   = (const float*)d_in[0];
    const float* emb = (const float*)d_in[1];
    // Defensive: identify by element count (x = 2097152, emb = 524288)
    if (n_in >= 2 && in_sizes[0] == NCODES * DIM && in_sizes[1] == QELEMS) {
        const float* t = x; x = emb; emb = t;
    }
    float* out = (float*)d_out;

    prep_kernel<<<NROWS / 256, 256>>>(emb);
    vq_main<<<(NROWS / 128) * NSPLIT, 256>>>(x, emb);
    gather_loss<<<512, 256>>>(x, emb, out, out + QELEMS + 2);
    finalize<<<1, 512>>>(out);
}